// round 17
// baseline (speedup 1.0000x reference)
#include <cuda_runtime.h>

#define BB 4
#define TT 32
#define DD 256
#define NN 1024
#define GROUP 32      // CTAs per batch group
#define COLS 32       // G columns owned per CTA
#define NTHR 512      // threads in main kernel (16 warps)
#define CANARY 0x7fffffffu   // NaN bit pattern; computed p values are never NaN

// ---------------- device scratch ----------------
__device__ float g_xn[BB*TT*NN];     // relu(ln(x@E))
__device__ float g_tn[BB*TT*NN];     // relu(ln(targets@E))
__device__ float g_p1[BB*TT*NN];     // p1 per (batch,step), canary-filled
__device__ float g_p2[BB*TT*NN];     // p2 per (batch,step), canary-filled
__device__ float g_reason[BB*TT*NN]; // max(p1,p2,p3)

// ---------------- dataflow primitives (data IS the flag) ----------------
__device__ __forceinline__ void publish2(float* p, float a0, float a1) {
  asm volatile("st.relaxed.gpu.global.v2.f32 [%0], {%1,%2};"
               :: "l"(p), "f"(a0), "f"(a1) : "memory");
}
__device__ __forceinline__ float2 poll2(const float* p) {
  float2 v;
  asm volatile("ld.relaxed.gpu.global.v2.f32 {%0,%1}, [%2];"
               : "=f"(v.x), "=f"(v.y) : "l"(p) : "memory");
  while (__float_as_uint(v.x) == CANARY) {
    asm volatile("ld.relaxed.gpu.global.v2.f32 {%0,%1}, [%2];"
                 : "=f"(v.x), "=f"(v.y) : "l"(p) : "memory");
  }
  return v;
}

// ---------------- kernel 1: neurons = relu(layernorm(X @ E)) ----------------
// 512 threads, 2 cols each (float2), explicit depth-8 LDG double buffering.
__global__ void __launch_bounds__(512) prep_kernel(const float* __restrict__ x_seq,
                                                   const float* __restrict__ targets,
                                                   const float* __restrict__ E) {
  __shared__ float xs[DD], ts[DD];
  __shared__ float2 red[16];
  int row = blockIdx.x;            // b*TT + t
  int tid = threadIdx.x;           // 0..511 -> cols {2tid, 2tid+1}
  int w = tid >> 5, l = tid & 31;

  // canary-fill g_p1 + g_p2
  {
    int gtid = row * 512 + tid;
    float c = __uint_as_float(CANARY);
    float2 cv; cv.x = c; cv.y = c;
    ((float2*)g_p1)[gtid] = cv;
    ((float2*)g_p2)[gtid] = cv;
  }

  if (tid < DD) {
    xs[tid] = x_seq[row*DD + tid];
    ts[tid] = targets[row*DD + tid];
  }
  __syncthreads();

  const float2* E2 = (const float2*)E;   // [256][512]
  float2 ax = make_float2(0.f, 0.f), at = make_float2(0.f, 0.f);
  float2 buf[8];
#pragma unroll
  for (int i = 0; i < 8; ++i) buf[i] = __ldg(E2 + i*512 + tid);

  for (int k0 = 0; k0 < DD; k0 += 8) {
    float2 cur[8];
#pragma unroll
    for (int i = 0; i < 8; ++i) cur[i] = buf[i];
    if (k0 + 8 < DD) {
#pragma unroll
      for (int i = 0; i < 8; ++i) buf[i] = __ldg(E2 + (k0 + 8 + i)*512 + tid);
    }
#pragma unroll
    for (int i = 0; i < 8; ++i) {
      float xv = xs[k0 + i], tv = ts[k0 + i];
      ax.x += xv*cur[i].x; ax.y += xv*cur[i].y;
      at.x += tv*cur[i].x; at.y += tv*cur[i].y;
    }
  }

  {
    float s1 = ax.x + ax.y, s2 = ax.x*ax.x + ax.y*ax.y;
#pragma unroll
    for (int o = 16; o; o >>= 1) {
      s1 += __shfl_xor_sync(0xffffffffu, s1, o);
      s2 += __shfl_xor_sync(0xffffffffu, s2, o);
    }
    if (l == 0) { red[w].x = s1; red[w].y = s2; }
    __syncthreads();
    float t1 = 0.f, t2 = 0.f;
#pragma unroll
    for (int i = 0; i < 16; ++i) { t1 += red[i].x; t2 += red[i].y; }
    float mu  = t1 * (1.0f/NN);
    float inv = rsqrtf(t2*(1.0f/NN) - mu*mu + 1e-5f);
    float2 o2;
    o2.x = fmaxf(0.f, (ax.x - mu)*inv);
    o2.y = fmaxf(0.f, (ax.y - mu)*inv);
    ((float2*)(g_xn + row*NN))[tid] = o2;
  }
  __syncthreads();
  {
    float s1 = at.x + at.y, s2 = at.x*at.x + at.y*at.y;
#pragma unroll
    for (int o = 16; o; o >>= 1) {
      s1 += __shfl_xor_sync(0xffffffffu, s1, o);
      s2 += __shfl_xor_sync(0xffffffffu, s2, o);
    }
    if (l == 0) { red[w].x = s1; red[w].y = s2; }
    __syncthreads();
    float t1 = 0.f, t2 = 0.f;
#pragma unroll
    for (int i = 0; i < 16; ++i) { t1 += red[i].x; t2 += red[i].y; }
    float mu  = t1 * (1.0f/NN);
    float inv = rsqrtf(t2*(1.0f/NN) - mu*mu + 1e-5f);
    float2 o2;
    o2.x = fmaxf(0.f, (at.x - mu)*inv);
    o2.y = fmaxf(0.f, (at.y - mu)*inv);
    ((float2*)(g_tn + row*NN))[tid] = o2;
  }
}

// ---------------- kernel 2: persistent scan, merged-loop 2-pass --------------
// Pass A step t: ONE j-loop computes p2(t-1) with G_{t-1} (gold) AND p1(t)
// with G_t (updated in-flight). xr regs hold x(t-1). One syncthreads/step.
__global__ void __launch_bounds__(NTHR, 1) main_kernel() {
  extern __shared__ float sm[];
  float* xall = sm;                 // TT*NN x-neurons (128 KB)
  float* tba  = xall + TT*NN;       // TT*COLS 0.5*tn values
  float* pb   = tba + TT*COLS;      // 2*NN ping-pong staged p vector
  float* rm   = pb + 2*NN;          // TT*COLS running max(p1,p2) per col

  int cta  = blockIdx.x;
  int b    = cta >> 5;
  int part = cta & 31;
  int mbase = part * COLS;
  int tid = threadIdx.x, w = tid >> 5, l = tid & 31;
  int cbase = mbase + w*2;

  // one-time preload
  {
    const float4* src = (const float4*)(g_xn + b*TT*NN);
    float4* dst = (float4*)xall;
    for (int i = tid; i < TT*NN/4; i += NTHR) dst[i] = src[i];
    for (int i = tid; i < TT*COLS; i += NTHR) {
      int t = i >> 5, c = i & 31;
      tba[i] = 0.5f * g_tn[(b*TT + t)*NN + mbase + c];
    }
  }
  __syncthreads();

  float gr0[32], gr1[32], xr[32];

#define INIT_G()                                                 \
  _Pragma("unroll")                                              \
  for (int j = 0; j < 32; ++j) {                                 \
    int n = l + 32*j;                                            \
    gr0[j] = (n == cbase)     ? 0.01f : 0.0f;                    \
    gr1[j] = (n == cbase + 1) ? 0.01f : 0.0f;                    \
  }

#define REDUCE2(a0, a1)                                          \
  _Pragma("unroll")                                              \
  for (int o = 16; o; o >>= 1) {                                 \
    a0 += __shfl_xor_sync(0xffffffffu, a0, o);                   \
    a1 += __shfl_xor_sync(0xffffffffu, a1, o);                   \
  }

  // ================= pass A =================
  INIT_G();
  // t = 0: p1(0) = x(0) . G_0, load xr
  {
    const float* xc = xall;
    float a0 = 0.f, a1 = 0.f;
#pragma unroll
    for (int j = 0; j < 32; ++j) {
      float xcv = xc[l + 32*j];
      xr[j] = xcv;
      a0 += xcv*gr0[j];
      a1 += xcv*gr1[j];
    }
    REDUCE2(a0, a1);
    if (l == 0) publish2(g_p1 + (b*TT)*NN + cbase, a0, a1);
  }

  for (int t = 1; t < TT; ++t) {
    float* pbuf = pb + (t & 1)*NN;
    {
      float2 v = poll2(g_p1 + (b*TT + t - 1)*NN + 2*tid);
      ((float2*)pbuf)[tid] = v;
    }
    __syncthreads();

    float tv0 = tba[t*COLS + w*2 + 0];
    float tv1 = tba[t*COLS + w*2 + 1];
    const float* xc = xall + t*NN;
    float aP1_0 = 0.f, aP1_1 = 0.f, aP2_0 = 0.f, aP2_1 = 0.f;
#pragma unroll
    for (int j = 0; j < 32; ++j) {
      float pv = pbuf[l + 32*j];
      float g0 = gr0[j], g1 = gr1[j];
      aP2_0 += pv*g0;                    // p2(t-1) with G_{t-1}
      aP2_1 += pv*g1;
      float xo = xr[j];
      g0 = fmaxf(g0, xo*tv0);            // G_t
      g1 = fmaxf(g1, xo*tv1);
      float xcv = xc[l + 32*j];
      aP1_0 += xcv*g0;                   // p1(t) with G_t
      aP1_1 += xcv*g1;
      gr0[j] = g0; gr1[j] = g1; xr[j] = xcv;
    }
#pragma unroll
    for (int o = 16; o; o >>= 1) {
      aP1_0 += __shfl_xor_sync(0xffffffffu, aP1_0, o);
      aP1_1 += __shfl_xor_sync(0xffffffffu, aP1_1, o);
      aP2_0 += __shfl_xor_sync(0xffffffffu, aP2_0, o);
      aP2_1 += __shfl_xor_sync(0xffffffffu, aP2_1, o);
    }
    if (l == 0) {
      publish2(g_p1 + (b*TT + t)*NN + cbase, aP1_0, aP1_1);      // critical first
      publish2(g_p2 + (b*TT + t - 1)*NN + cbase, aP2_0, aP2_1);
      rm[(t-1)*COLS + w*2 + 0] = fmaxf(pbuf[cbase],     aP2_0);
      rm[(t-1)*COLS + w*2 + 1] = fmaxf(pbuf[cbase + 1], aP2_1);
    }
  }

  // epilogue: p2(TT-1) = p1(TT-1) . G_{TT-1}
  {
    float* pbuf = pb + (TT & 1)*NN;   // buf 0; step TT-1 used buf 1
    {
      float2 v = poll2(g_p1 + (b*TT + TT - 1)*NN + 2*tid);
      ((float2*)pbuf)[tid] = v;
    }
    __syncthreads();
    float a0 = 0.f, a1 = 0.f;
#pragma unroll
    for (int j = 0; j < 32; ++j) {
      float pv = pbuf[l + 32*j];
      a0 += pv*gr0[j];
      a1 += pv*gr1[j];
    }
    REDUCE2(a0, a1);
    if (l == 0) {
      publish2(g_p2 + (b*TT + TT - 1)*NN + cbase, a0, a1);
      rm[(TT-1)*COLS + w*2 + 0] = fmaxf(pbuf[cbase],     a0);
      rm[(TT-1)*COLS + w*2 + 1] = fmaxf(pbuf[cbase + 1], a1);
    }
    __syncthreads();   // pass boundary: protect pbuf + rm
  }

  // ================= pass B: p3(t) = p2(t) . G_t =================
  INIT_G();
  for (int t = 0; t < TT; ++t) {
    float* pbuf = pb + (t & 1)*NN;
    {
      float2 v = poll2(g_p2 + (b*TT + t)*NN + 2*tid);
      ((float2*)pbuf)[tid] = v;
    }
    __syncthreads();

    const float* xc = xall + t*NN;
    float a0 = 0.f, a1 = 0.f;
    if (t > 0) {
      float tv0 = tba[t*COLS + w*2 + 0];
      float tv1 = tba[t*COLS + w*2 + 1];
#pragma unroll
      for (int j = 0; j < 32; ++j) {
        float g0 = gr0[j], g1 = gr1[j];
        float xo = xr[j];
        g0 = fmaxf(g0, xo*tv0);
        g1 = fmaxf(g1, xo*tv1);
        float pv = pbuf[l + 32*j];
        a0 += pv*g0;
        a1 += pv*g1;
        gr0[j] = g0; gr1[j] = g1; xr[j] = xc[l + 32*j];
      }
    } else {
#pragma unroll
      for (int j = 0; j < 32; ++j) {
        float pv = pbuf[l + 32*j];
        a0 += pv*gr0[j];
        a1 += pv*gr1[j];
        xr[j] = xc[l + 32*j];
      }
    }
    REDUCE2(a0, a1);
    if (l == 0) {
      float2 st;
      st.x = fmaxf(rm[t*COLS + w*2 + 0], a0);
      st.y = fmaxf(rm[t*COLS + w*2 + 1], a1);
      *(float2*)(&g_reason[(b*TT + t)*NN + cbase]) = st;
    }
  }
}

// ---------------- kernel 3: y = relu(reasoning @ Dy) ----------------
__global__ void __launch_bounds__(256) out_kernel(const float* __restrict__ Dy,
                                                  float* __restrict__ out) {
  __shared__ float rs[4*NN];
  int rbase = blockIdx.x * 4;      // grid 32 -> 128 rows
  int tid = threadIdx.x;
  int c4 = tid & 63;               // float4 column group
  int r  = tid >> 6;               // row within block (0..3)
  for (int i = tid; i < 4*NN; i += 256) rs[i] = g_reason[rbase*NN + i];
  __syncthreads();

  const float4* Dy4 = (const float4*)Dy;  // [1024][64] float4
  const float* rr = rs + r*NN;
  float4 a = make_float4(0.f,0.f,0.f,0.f);
#pragma unroll 8
  for (int n = 0; n < NN; ++n) {
    float4 d = Dy4[n*64 + c4];
    float pv = rr[n];
    a.x += pv*d.x; a.y += pv*d.y; a.z += pv*d.z; a.w += pv*d.w;
  }
  float4 o;
  o.x = fmaxf(a.x,0.f); o.y = fmaxf(a.y,0.f);
  o.z = fmaxf(a.z,0.f); o.w = fmaxf(a.w,0.f);
  ((float4*)(out + (rbase + r)*DD))[c4] = o;
}

// ---------------- launch ----------------
extern "C" void kernel_launch(void* const* d_in, const int* in_sizes, int n_in,
                              void* d_out, int out_size) {
  const float* x_seq   = (const float*)d_in[0];  // [4,32,256]
  const float* targets = (const float*)d_in[1];  // [4,32,256]
  const float* E       = (const float*)d_in[2];  // [256,1024]
  const float* Dy      = (const float*)d_in[3];  // [1024,256]
  float* out = (float*)d_out;                    // [4,32,256]

  int smem = (TT*NN + TT*COLS + 2*NN + TT*COLS) * (int)sizeof(float);  // ~148 KB
  static int smem_set = 0;
  if (!smem_set) {
    cudaFuncSetAttribute(main_kernel, cudaFuncAttributeMaxDynamicSharedMemorySize, smem);
    smem_set = 1;
  }

  prep_kernel<<<BB*TT, 512>>>(x_seq, targets, E);   // also canary-fills g_p1/g_p2
  main_kernel<<<BB*GROUP, NTHR, smem>>>();
  out_kernel<<<32, 256>>>(Dy, out);
}